// round 12
// baseline (speedup 1.0000x reference)
#include <cuda_runtime.h>
#include <cuda_fp16.h>
#include <math.h>

// Problem constants
#define Bn 4
#define Sn 2048
#define Dn 1024
#define Hn 16
#define HDn 64
#define N3 3072   // 3*Dn

// ---------------------------------------------------------------------------
// Device scratch (referenced ONLY in device code — R5 ATS lesson)
// ---------------------------------------------------------------------------
__device__ __half g_xh[(size_t)Bn * Sn * Dn];        // x as half [m][k]
__device__ __half g_wqkvh[(size_t)Dn * N3];          // W_qkv half [k][n]
__device__ __half g_wouth[(size_t)Dn * Dn];          // W_out half [k][n]
__device__ __half g_qh[(size_t)Bn * Hn * Sn * HDn];  // pre-scaled by 1/8
__device__ __half g_kh[(size_t)Bn * Hn * Sn * HDn];
__device__ __half g_vh[(size_t)Bn * Hn * HDn * Sn];  // [Hd][S] transposed
__device__ __half g_ctxh[(size_t)Bn * Sn * Dn];
__device__ float  g_proj[(size_t)Bn * Sn * Dn];

// Pack two floats -> f16x2 (lo = first elem, hi = second).
#define F22H(u, lo, hi)                                                      \
  asm("cvt.rn.f16x2.f32 %0, %1, %2;" : "=r"(u) : "f"(hi), "f"(lo))

// fp16 mma, fp32 accumulate; macro binds operands to lvalues (no lmem).
#define MMA_F16(c0, c1, c2, c3, a0, a1, a2, a3, b0, b1)                      \
  asm volatile(                                                              \
      "mma.sync.aligned.m16n8k16.row.col.f32.f16.f16.f32 "                   \
      "{%0,%1,%2,%3},{%4,%5,%6,%7},{%8,%9},{%0,%1,%2,%3};"                   \
      : "+f"(c0), "+f"(c1), "+f"(c2), "+f"(c3)                               \
      : "r"(a0), "r"(a1), "r"(a2), "r"(a3), "r"(b0), "r"(b1))

#define LDSM4(d0, d1, d2, d3, a)                                             \
  asm volatile(                                                              \
      "ldmatrix.sync.aligned.m8n8.x4.shared.b16 {%0,%1,%2,%3},[%4];"         \
      : "=r"(d0), "=r"(d1), "=r"(d2), "=r"(d3) : "r"(a))
#define LDSM4T(d0, d1, d2, d3, a)                                            \
  asm volatile(                                                              \
      "ldmatrix.sync.aligned.m8n8.x4.trans.shared.b16 {%0,%1,%2,%3},[%4];"   \
      : "=r"(d0), "=r"(d1), "=r"(d2), "=r"(d3) : "r"(a))

#define SMEM_U32(p) ((unsigned)__cvta_generic_to_shared(p))

// cp.async 16B, L1-bypass
#define CPA16(dst, src)                                                      \
  asm volatile("cp.async.cg.shared.global [%0], [%1], 16;" ::                \
               "r"(dst), "l"(src))
#define CPA_COMMIT() asm volatile("cp.async.commit_group;")
#define CPA_WAIT0()  asm volatile("cp.async.wait_group 0;")

// ---------------------------------------------------------------------------
// Conversion kernels (once per launch; deterministic)
// ---------------------------------------------------------------------------
__global__ __launch_bounds__(256) void cvt_x_kernel(const float* __restrict__ x) {
  const size_t i = ((size_t)blockIdx.x * 256 + threadIdx.x) * 4;
  float4 v = *(const float4*)&x[i];
  unsigned u0, u1;
  F22H(u0, v.x, v.y);
  F22H(u1, v.z, v.w);
  *(uint2*)&g_xh[i] = make_uint2(u0, u1);
}

template <int WHICH>   // 1 = qkv, 0 = out
__global__ __launch_bounds__(256) void cvt_w_kernel(const float* __restrict__ W) {
  const size_t i = ((size_t)blockIdx.x * 256 + threadIdx.x) * 4;
  float4 v = *(const float4*)&W[i];
  unsigned u0, u1;
  F22H(u0, v.x, v.y);
  F22H(u1, v.z, v.w);
  __half* dst = WHICH ? g_wqkvh : g_wouth;
  *(uint2*)&dst[i] = make_uint2(u0, u1);
}

// ---------------------------------------------------------------------------
// QKV scatter epilogue helper
// ---------------------------------------------------------------------------
__device__ __forceinline__ void scatter_qkv(int m, int n, float val) {
  const int sec = n >> 10;
  const int h   = (n & 1023) >> 6;
  const int hd  = n & 63;
  const int b   = m >> 11;
  const int s   = m & 2047;
  if (sec == 0)
    g_qh[((size_t)(b * Hn + h) * Sn + s) * HDn + hd] =
        __float2half_rn(val * 0.125f);
  else if (sec == 1)
    g_kh[((size_t)(b * Hn + h) * Sn + s) * HDn + hd] = __float2half_rn(val);
  else
    g_vh[((size_t)(b * Hn + h) * HDn + hd) * Sn + s] = __float2half_rn(val);
}

// ---------------------------------------------------------------------------
// FP16 GEMM: CTA 128x256, BK=32, 256 threads, 8 warps 2(M)x4(N),
// warp tile 64x64. 2-stage cp.async double buffer (same pattern as the
// attention kernel), ldmatrix fragments.
// Dynamic smem (halfs): A stage s at s*5120 (128 rows x 40);
//                       B stage s at 10240 + s*8448 (32 rows x 264).
// Total 27136 halfs = 54272 B.
// ---------------------------------------------------------------------------
#define GEMM_SMEM_BYTES 54272
#define G_NIT (Dn / 32)

#define GEMM_ISSUE(s, kk)                                                    \
  {                                                                          \
    { int idx = t;       int row = idx >> 2, c = (idx & 3) * 8;              \
      CPA16(SMEM_U32(&sg[(s) * 5120 + row * 40 + c]),                        \
            &Ah[(size_t)(m0 + row) * Dn + (kk) + c]); }                      \
    { int idx = t + 256; int row = idx >> 2, c = (idx & 3) * 8;              \
      CPA16(SMEM_U32(&sg[(s) * 5120 + row * 40 + c]),                        \
            &Ah[(size_t)(m0 + row) * Dn + (kk) + c]); }                      \
    { int idx = t;       int row = idx >> 5, c = (idx & 31) * 8;             \
      CPA16(SMEM_U32(&sg[10240 + (s) * 8448 + row * 264 + c]),               \
            &Wh[(size_t)((kk) + row) * NDIM + n0 + c]); }                    \
    { int idx = t + 256; int row = idx >> 5, c = (idx & 31) * 8;             \
      CPA16(SMEM_U32(&sg[10240 + (s) * 8448 + row * 264 + c]),               \
            &Wh[(size_t)((kk) + row) * NDIM + n0 + c]); }                    \
    { int idx = t + 512; int row = idx >> 5, c = (idx & 31) * 8;             \
      CPA16(SMEM_U32(&sg[10240 + (s) * 8448 + row * 264 + c]),               \
            &Wh[(size_t)((kk) + row) * NDIM + n0 + c]); }                    \
    { int idx = t + 768; int row = idx >> 5, c = (idx & 31) * 8;             \
      CPA16(SMEM_U32(&sg[10240 + (s) * 8448 + row * 264 + c]),               \
            &Wh[(size_t)((kk) + row) * NDIM + n0 + c]); }                    \
    CPA_COMMIT();                                                            \
  }

template <int NDIM, int MODE>
__global__ __launch_bounds__(256, 1) void gemm_f16_kernel(
    const float* __restrict__ bias) {
  extern __shared__ __align__(16) __half sg[];

  const __half* __restrict__ Ah = (MODE == 1) ? g_xh : g_ctxh;
  const __half* __restrict__ Wh = (MODE == 1) ? g_wqkvh : g_wouth;

  const int t    = threadIdx.x;
  const int lane = t & 31;
  const int lq   = lane >> 2;
  const int lt   = lane & 3;
  const int warp = t >> 5;
  const int wm   = warp >> 2;   // 0..1 -> 64 rows
  const int wn   = warp & 3;    // 0..3 -> 64 cols
  const int n0   = blockIdx.x * 256;
  const int m0   = blockIdx.y * 128;

  const int l8  = lane & 7;
  const int mhi = (lane >> 3) & 1;
  const int mvh = (lane >> 4) & 1;

  float acc[4][8][4];
#pragma unroll
  for (int mt = 0; mt < 4; mt++)
#pragma unroll
    for (int nt = 0; nt < 8; nt++)
#pragma unroll
      for (int j = 0; j < 4; j++) acc[mt][nt][j] = 0.0f;

  GEMM_ISSUE(0, 0)
  CPA_WAIT0();
  __syncthreads();

  for (int it = 0; it < G_NIT; it++) {
    const int s = it & 1;
    if (it + 1 < G_NIT) GEMM_ISSUE(1 - s, (it + 1) * 32)

    const int sA = s * 5120;
    const int sB = 10240 + s * 8448;
#pragma unroll
    for (int ks = 0; ks < 2; ks++) {
      const int kb = ks * 16;
      unsigned a[4][4];
#pragma unroll
      for (int mt = 0; mt < 4; mt++) {
        const int rowA = wm * 64 + mt * 16 + mhi * 8 + l8;
        const int kA   = kb + mvh * 8;
        LDSM4(a[mt][0], a[mt][1], a[mt][2], a[mt][3],
              SMEM_U32(&sg[sA + rowA * 40 + kA]));
      }
#pragma unroll
      for (int ng = 0; ng < 4; ng++) {
        const int krow = kb + mhi * 8 + l8;
        const int nB   = wn * 64 + ng * 16 + mvh * 8;
        unsigned b0, b1, b2, b3;
        LDSM4T(b0, b1, b2, b3, SMEM_U32(&sg[sB + krow * 264 + nB]));
        const int nt0 = ng * 2, nt1 = ng * 2 + 1;
#pragma unroll
        for (int mt = 0; mt < 4; mt++) {
          MMA_F16(acc[mt][nt0][0], acc[mt][nt0][1], acc[mt][nt0][2],
                  acc[mt][nt0][3], a[mt][0], a[mt][1], a[mt][2], a[mt][3],
                  b0, b1);
          MMA_F16(acc[mt][nt1][0], acc[mt][nt1][1], acc[mt][nt1][2],
                  acc[mt][nt1][3], a[mt][0], a[mt][1], a[mt][2], a[mt][3],
                  b2, b3);
        }
      }
    }
    if (it + 1 < G_NIT) CPA_WAIT0();
    __syncthreads();
  }

  // Epilogue
#pragma unroll
  for (int mt = 0; mt < 4; mt++) {
    const int r0 = m0 + wm * 64 + mt * 16 + lq;
#pragma unroll
    for (int nt = 0; nt < 8; nt++) {
      const int c0 = n0 + wn * 64 + nt * 8 + lt * 2;
      float v0 = acc[mt][nt][0] + bias[c0];
      float v1 = acc[mt][nt][1] + bias[c0 + 1];
      float v2 = acc[mt][nt][2] + bias[c0];
      float v3 = acc[mt][nt][3] + bias[c0 + 1];
      if (MODE == 0) {
        g_proj[(size_t)r0 * Dn + c0]           = v0;
        g_proj[(size_t)r0 * Dn + c0 + 1]       = v1;
        g_proj[(size_t)(r0 + 8) * Dn + c0]     = v2;
        g_proj[(size_t)(r0 + 8) * Dn + c0 + 1] = v3;
      } else {
        scatter_qkv(r0, c0, v0);
        scatter_qkv(r0, c0 + 1, v1);
        scatter_qkv(r0 + 8, c0, v2);
        scatter_qkv(r0 + 8, c0 + 1, v3);
      }
    }
  }
}

// ---------------------------------------------------------------------------
// Flash attention (FA2): 8 warps x 16-row stripes, register softmax,
// Q fragments hoisted, ldmatrix fragments, cp.async double-buffered K/V.
// Smem halfs: Q [128][88] at 0; stage s: K at 11264+s*11264 (64x88),
// V at +5632. Total 33792 halfs = 67584 B.
// ---------------------------------------------------------------------------
#define ATTN_SMEM_BYTES 67584
#define A_NIT (Sn / 64)

#define ATT_ISSUE(s, kk)                                                     \
  {                                                                          \
    const int ksb_ = 11264 + (s) * 11264;                                    \
    const int vsb_ = ksb_ + 5632;                                            \
    { int idx = t;       int row = idx >> 3, c = (idx & 7) * 8;              \
      CPA16(SMEM_U32(&smh[ksb_ + row * 88 + c]),                             \
            &g_kh[baseQK + (size_t)((kk) + row) * HDn + c]);                 \
      CPA16(SMEM_U32(&smh[vsb_ + row * 88 + c]),                             \
            &g_vh[baseV + (size_t)row * Sn + (kk) + c]); }                   \
    { int idx = t + 256; int row = idx >> 3, c = (idx & 7) * 8;              \
      CPA16(SMEM_U32(&smh[ksb_ + row * 88 + c]),                             \
            &g_kh[baseQK + (size_t)((kk) + row) * HDn + c]);                 \
      CPA16(SMEM_U32(&smh[vsb_ + row * 88 + c]),                             \
            &g_vh[baseV + (size_t)row * Sn + (kk) + c]); }                   \
    CPA_COMMIT();                                                            \
  }

__global__ __launch_bounds__(256) void attn_f16_kernel() {
  extern __shared__ __align__(16) __half smh[];

  const int t    = threadIdx.x;
  const int lane = t & 31;
  const int warp = t >> 5;
  const int rw   = warp * 16;
  const int b    = blockIdx.z;
  const int h    = blockIdx.y;
  const int sQ   = blockIdx.x * 128;

  const int l8  = lane & 7;
  const int mhi = (lane >> 3) & 1;
  const int mvh = (lane >> 4) & 1;

  const size_t baseQK = (size_t)(b * Hn + h) * Sn * HDn;
  const size_t baseV  = (size_t)(b * Hn + h) * HDn * Sn;

  // Q tile plain copy
#pragma unroll
  for (int i = 0; i < 4; i++) {
    int idx = t + i * 256;
    int row = idx >> 3, c = (idx & 7) * 8;
    *(uint4*)&smh[row * 88 + c] =
        *(const uint4*)&g_qh[baseQK + (size_t)(sQ + row) * HDn + c];
  }

  ATT_ISSUE(0, 0)
  CPA_WAIT0();
  __syncthreads();

  // Hoist Q A-fragments
  unsigned qa[4][4];
#pragma unroll
  for (int ks = 0; ks < 4; ks++) {
    const int rowQ = rw + mhi * 8 + l8;
    const int kQ   = ks * 16 + mvh * 8;
    LDSM4(qa[ks][0], qa[ks][1], qa[ks][2], qa[ks][3],
          SMEM_U32(&smh[rowQ * 88 + kQ]));
  }

  float m0 = -INFINITY, m1 = -INFINITY, l0 = 0.0f, l1 = 0.0f;
  float o[8][4];
#pragma unroll
  for (int nd = 0; nd < 8; nd++)
#pragma unroll
    for (int j = 0; j < 4; j++) o[nd][j] = 0.0f;

  for (int it = 0; it < A_NIT; it++) {
    const int ksb = 11264 + (it & 1) * 11264;
    const int vsb = ksb + 5632;
    if (it + 1 < A_NIT) ATT_ISSUE((it + 1) & 1, (it + 1) * 64)

    // S = Q K^T
    float sa[8][4];
#pragma unroll
    for (int nt = 0; nt < 8; nt++)
#pragma unroll
      for (int j = 0; j < 4; j++) sa[nt][j] = 0.0f;

#pragma unroll
    for (int ks = 0; ks < 4; ks++) {
#pragma unroll
      for (int ng = 0; ng < 4; ng++) {
        const int nrow = ng * 16 + mvh * 8 + l8;
        const int kofs = ks * 16 + mhi * 8;
        unsigned b0, b1, b2, b3;
        LDSM4(b0, b1, b2, b3, SMEM_U32(&smh[ksb + nrow * 88 + kofs]));
        const int nt0 = ng * 2, nt1 = ng * 2 + 1;
        MMA_F16(sa[nt0][0], sa[nt0][1], sa[nt0][2], sa[nt0][3],
                qa[ks][0], qa[ks][1], qa[ks][2], qa[ks][3], b0, b1);
        MMA_F16(sa[nt1][0], sa[nt1][1], sa[nt1][2], sa[nt1][3],
                qa[ks][0], qa[ks][1], qa[ks][2], qa[ks][3], b2, b3);
      }
    }

    // Register softmax
    float mx0 = -INFINITY, mx1 = -INFINITY;
#pragma unroll
    for (int nt = 0; nt < 8; nt++) {
      mx0 = fmaxf(mx0, fmaxf(sa[nt][0], sa[nt][1]));
      mx1 = fmaxf(mx1, fmaxf(sa[nt][2], sa[nt][3]));
    }
    mx0 = fmaxf(mx0, __shfl_xor_sync(0xffffffffu, mx0, 1));
    mx0 = fmaxf(mx0, __shfl_xor_sync(0xffffffffu, mx0, 2));
    mx1 = fmaxf(mx1, __shfl_xor_sync(0xffffffffu, mx1, 1));
    mx1 = fmaxf(mx1, __shfl_xor_sync(0xffffffffu, mx1, 2));
    const float mn0 = fmaxf(m0, mx0);
    const float mn1 = fmaxf(m1, mx1);
    const float cr0 = __expf(m0 - mn0);
    const float cr1 = __expf(m1 - mn1);
    m0 = mn0; m1 = mn1;

    float sum0 = 0.0f, sum1 = 0.0f;
#pragma unroll
    for (int nt = 0; nt < 8; nt++) {
      sa[nt][0] = __expf(sa[nt][0] - mn0);
      sa[nt][1] = __expf(sa[nt][1] - mn0);
      sa[nt][2] = __expf(sa[nt][2] - mn1);
      sa[nt][3] = __expf(sa[nt][3] - mn1);
      sum0 += sa[nt][0] + sa[nt][1];
      sum1 += sa[nt][2] + sa[nt][3];
    }
    sum0 += __shfl_xor_sync(0xffffffffu, sum0, 1);
    sum0 += __shfl_xor_sync(0xffffffffu, sum0, 2);
    sum1 += __shfl_xor_sync(0xffffffffu, sum1, 1);
    sum1 += __shfl_xor_sync(0xffffffffu, sum1, 2);
    l0 = l0 * cr0 + sum0;
    l1 = l1 * cr1 + sum1;

#pragma unroll
    for (int nd = 0; nd < 8; nd++) {
      o[nd][0] *= cr0; o[nd][1] *= cr0;
      o[nd][2] *= cr1; o[nd][3] *= cr1;
    }

    // O += P @ V
#pragma unroll
    for (int kp = 0; kp < 4; kp++) {
      unsigned pa0, pa1, pa2, pa3;
      F22H(pa0, sa[2 * kp][0], sa[2 * kp][1]);
      F22H(pa1, sa[2 * kp][2], sa[2 * kp][3]);
      F22H(pa2, sa[2 * kp + 1][0], sa[2 * kp + 1][1]);
      F22H(pa3, sa[2 * kp + 1][2], sa[2 * kp + 1][3]);
#pragma unroll
      for (int ng = 0; ng < 4; ng++) {
        const int drow = ng * 16 + mvh * 8 + l8;
        const int kofs = kp * 16 + mhi * 8;
        unsigned b0, b1, b2, b3;
        LDSM4(b0, b1, b2, b3, SMEM_U32(&smh[vsb + drow * 88 + kofs]));
        const int nd0 = ng * 2, nd1 = ng * 2 + 1;
        MMA_F16(o[nd0][0], o[nd0][1], o[nd0][2], o[nd0][3],
                pa0, pa1, pa2, pa3, b0, b1);
        MMA_F16(o[nd1][0], o[nd1][1], o[nd1][2], o[nd1][3],
                pa0, pa1, pa2, pa3, b2, b3);
      }
    }

    if (it + 1 < A_NIT) CPA_WAIT0();
    __syncthreads();
  }

  const int lq = lane >> 2;
  const int lt = lane & 3;
  const float i0 = 1.0f / l0;
  const float i1 = 1.0f / l1;
  const size_t row0 = (size_t)(b * Sn + sQ + rw + lq) * Dn + h * HDn;
  const size_t row1 = (size_t)(b * Sn + sQ + rw + lq + 8) * Dn + h * HDn;
#pragma unroll
  for (int nd = 0; nd < 8; nd++) {
    const int c = nd * 8 + lt * 2;
    unsigned u0, u1;
    F22H(u0, o[nd][0] * i0, o[nd][1] * i0);
    F22H(u1, o[nd][2] * i1, o[nd][3] * i1);
    *(unsigned*)&g_ctxh[row0 + c] = u0;
    *(unsigned*)&g_ctxh[row1 + c] = u1;
  }
}

// ---------------------------------------------------------------------------
// Residual + LayerNorm (fp32, unchanged)
// ---------------------------------------------------------------------------
__device__ __forceinline__ float block_sum(float v, float* red) {
#pragma unroll
  for (int o = 16; o; o >>= 1) v += __shfl_xor_sync(0xffffffffu, v, o);
  if ((threadIdx.x & 31) == 0) red[threadIdx.x >> 5] = v;
  __syncthreads();
  float tot = red[0] + red[1] + red[2] + red[3] +
              red[4] + red[5] + red[6] + red[7];
  __syncthreads();
  return tot;
}

__global__ __launch_bounds__(256) void ln_kernel(
    const float* __restrict__ x, const float* __restrict__ gamma,
    const float* __restrict__ beta, float* __restrict__ out) {
  __shared__ float red[8];
  const int row = blockIdx.x;
  const int c   = threadIdx.x * 4;

  float4 y  = *(const float4*)&g_proj[(size_t)row * Dn + c];
  float4 xv = *(const float4*)&x[(size_t)row * Dn + c];
  y.x += xv.x; y.y += xv.y; y.z += xv.z; y.w += xv.w;

  float tot = block_sum(y.x + y.y + y.z + y.w, red);
  const float mu = tot * (1.0f / Dn);

  float dx = y.x - mu, dy = y.y - mu, dz = y.z - mu, dw = y.w - mu;
  float sq = block_sum(dx * dx + dy * dy + dz * dz + dw * dw, red);
  const float var = sq * (1.0f / Dn);
  const float r = rsqrtf(var + 1e-5f);

  float4 g  = *(const float4*)&gamma[c];
  float4 bt = *(const float4*)&beta[c];
  float4 o;
  o.x = dx * r * g.x + bt.x;
  o.y = dy * r * g.y + bt.y;
  o.z = dz * r * g.z + bt.z;
  o.w = dw * r * g.w + bt.w;
  *(float4*)&out[(size_t)row * Dn + c] = o;
}

// ---------------------------------------------------------------------------
// Launch — only harness pointers cross the host/device boundary.
// ---------------------------------------------------------------------------
extern "C" void kernel_launch(void* const* d_in, const int* in_sizes, int n_in,
                              void* d_out, int out_size) {
  (void)in_sizes; (void)n_in; (void)out_size;
  const float* x     = (const float*)d_in[0];
  const float* W_qkv = (const float*)d_in[1];
  const float* b_qkv = (const float*)d_in[2];
  const float* W_out = (const float*)d_in[3];
  const float* b_out = (const float*)d_in[4];
  const float* gamma = (const float*)d_in[5];
  const float* beta  = (const float*)d_in[6];
  float* out = (float*)d_out;

  cudaFuncSetAttribute(attn_f16_kernel,
                       cudaFuncAttributeMaxDynamicSharedMemorySize,
                       ATTN_SMEM_BYTES);
  cudaFuncSetAttribute(gemm_f16_kernel<N3, 1>,
                       cudaFuncAttributeMaxDynamicSharedMemorySize,
                       GEMM_SMEM_BYTES);
  cudaFuncSetAttribute(gemm_f16_kernel<Dn, 0>,
                       cudaFuncAttributeMaxDynamicSharedMemorySize,
                       GEMM_SMEM_BYTES);

  cvt_x_kernel<<<(Bn * Sn * Dn) / 1024, 256>>>(x);
  cvt_w_kernel<1><<<(Dn * N3) / 1024, 256>>>(W_qkv);
  cvt_w_kernel<0><<<(Dn * Dn) / 1024, 256>>>(W_out);

  gemm_f16_kernel<N3, 1>
      <<<dim3(N3 / 256, (Bn * Sn) / 128), 256, GEMM_SMEM_BYTES>>>(b_qkv);
  attn_f16_kernel<<<dim3(Sn / 128, Hn, Bn), 256, ATTN_SMEM_BYTES>>>();
  gemm_f16_kernel<Dn, 0>
      <<<dim3(Dn / 256, (Bn * Sn) / 128), 256, GEMM_SMEM_BYTES>>>(b_out);
  ln_kernel<<<Bn * Sn, 256>>>(x, gamma, beta, out);
}

// round 14
// speedup vs baseline: 1.0926x; 1.0926x over previous
#include <cuda_runtime.h>
#include <cuda_fp16.h>
#include <math.h>

// Problem constants
#define Bn 4
#define Sn 2048
#define Dn 1024
#define Hn 16
#define HDn 64
#define N3 3072   // 3*Dn

// ---------------------------------------------------------------------------
// Device scratch (referenced ONLY in device code — R5 ATS lesson)
// ---------------------------------------------------------------------------
__device__ __half g_xh[(size_t)Bn * Sn * Dn];        // x as half [m][k]
__device__ __half g_wqkvh[(size_t)Dn * N3];          // W_qkv half [k][n]
__device__ __half g_wouth[(size_t)Dn * Dn];          // W_out half [k][n]
__device__ __half g_qh[(size_t)Bn * Hn * Sn * HDn];  // pre-scaled by 1/8
__device__ __half g_kh[(size_t)Bn * Hn * Sn * HDn];
__device__ __half g_vh[(size_t)Bn * Hn * HDn * Sn];  // [Hd][S] transposed
__device__ __half g_ctxh[(size_t)Bn * Sn * Dn];
__device__ float  g_proj[(size_t)Bn * Sn * Dn];

// Pack two floats -> f16x2 (lo = first elem, hi = second).
#define F22H(u, lo, hi)                                                      \
  asm("cvt.rn.f16x2.f32 %0, %1, %2;" : "=r"(u) : "f"(hi), "f"(lo))

// fp16 mma, fp32 accumulate; macro binds operands to lvalues (no lmem).
#define MMA_F16(c0, c1, c2, c3, a0, a1, a2, a3, b0, b1)                      \
  asm volatile(                                                              \
      "mma.sync.aligned.m16n8k16.row.col.f32.f16.f16.f32 "                   \
      "{%0,%1,%2,%3},{%4,%5,%6,%7},{%8,%9},{%0,%1,%2,%3};"                   \
      : "+f"(c0), "+f"(c1), "+f"(c2), "+f"(c3)                               \
      : "r"(a0), "r"(a1), "r"(a2), "r"(a3), "r"(b0), "r"(b1))

#define LDSM4(d0, d1, d2, d3, a)                                             \
  asm volatile(                                                              \
      "ldmatrix.sync.aligned.m8n8.x4.shared.b16 {%0,%1,%2,%3},[%4];"         \
      : "=r"(d0), "=r"(d1), "=r"(d2), "=r"(d3) : "r"(a))
#define LDSM4T(d0, d1, d2, d3, a)                                            \
  asm volatile(                                                              \
      "ldmatrix.sync.aligned.m8n8.x4.trans.shared.b16 {%0,%1,%2,%3},[%4];"   \
      : "=r"(d0), "=r"(d1), "=r"(d2), "=r"(d3) : "r"(a))

#define SMEM_U32(p) ((unsigned)__cvta_generic_to_shared(p))

// cp.async 16B, L1-bypass
#define CPA16(dst, src)                                                      \
  asm volatile("cp.async.cg.shared.global [%0], [%1], 16;" ::                \
               "r"(dst), "l"(src))
#define CPA_COMMIT() asm volatile("cp.async.commit_group;")
#define CPA_WAIT0()  asm volatile("cp.async.wait_group 0;")

// ---------------------------------------------------------------------------
// Conversion kernels (once per launch; deterministic)
// ---------------------------------------------------------------------------
__global__ __launch_bounds__(256) void cvt_x_kernel(const float* __restrict__ x) {
  const size_t i = ((size_t)blockIdx.x * 256 + threadIdx.x) * 4;
  float4 v = *(const float4*)&x[i];
  unsigned u0, u1;
  F22H(u0, v.x, v.y);
  F22H(u1, v.z, v.w);
  *(uint2*)&g_xh[i] = make_uint2(u0, u1);
}

template <int WHICH>   // 1 = qkv, 0 = out
__global__ __launch_bounds__(256) void cvt_w_kernel(const float* __restrict__ W) {
  const size_t i = ((size_t)blockIdx.x * 256 + threadIdx.x) * 4;
  float4 v = *(const float4*)&W[i];
  unsigned u0, u1;
  F22H(u0, v.x, v.y);
  F22H(u1, v.z, v.w);
  __half* dst = WHICH ? g_wqkvh : g_wouth;
  *(uint2*)&dst[i] = make_uint2(u0, u1);
}

// ---------------------------------------------------------------------------
// QKV scatter epilogue helper
// ---------------------------------------------------------------------------
__device__ __forceinline__ void scatter_qkv(int m, int n, float val) {
  const int sec = n >> 10;
  const int h   = (n & 1023) >> 6;
  const int hd  = n & 63;
  const int b   = m >> 11;
  const int s   = m & 2047;
  if (sec == 0)
    g_qh[((size_t)(b * Hn + h) * Sn + s) * HDn + hd] =
        __float2half_rn(val * 0.125f);
  else if (sec == 1)
    g_kh[((size_t)(b * Hn + h) * Sn + s) * HDn + hd] = __float2half_rn(val);
  else
    g_vh[((size_t)(b * Hn + h) * HDn + hd) * Sn + s] = __float2half_rn(val);
}

// ---------------------------------------------------------------------------
// FP16 GEMM: CTA 128x128, BK=32, 256 threads, 8 warps 4(M)x2(N),
// warp tile 32x64 (R9 config: 128 regs -> 2 CTAs/SM) + 2-stage cp.async
// (R12's traffic fix). Static smem:
//   A stage s: [128][40] halfs at s*5120;  B stage s: [32][136] at 10240+s*4352.
//   Total 18944 halfs = 37888 B -> 2 CTAs/SM.
// ---------------------------------------------------------------------------
#define G_NIT (Dn / 32)

#define GEMM_ISSUE(s, kk)                                                    \
  {                                                                          \
    { int idx = t;       int row = idx >> 2, c = (idx & 3) * 8;              \
      CPA16(SMEM_U32(&sg[(s) * 5120 + row * 40 + c]),                        \
            &Ah[(size_t)(m0 + row) * Dn + (kk) + c]); }                      \
    { int idx = t + 256; int row = idx >> 2, c = (idx & 3) * 8;              \
      CPA16(SMEM_U32(&sg[(s) * 5120 + row * 40 + c]),                        \
            &Ah[(size_t)(m0 + row) * Dn + (kk) + c]); }                      \
    { int idx = t;       int row = idx >> 4, c = (idx & 15) * 8;             \
      CPA16(SMEM_U32(&sg[10240 + (s) * 4352 + row * 136 + c]),               \
            &Wh[(size_t)((kk) + row) * NDIM + n0 + c]); }                    \
    { int idx = t + 256; int row = idx >> 4, c = (idx & 15) * 8;             \
      CPA16(SMEM_U32(&sg[10240 + (s) * 4352 + row * 136 + c]),               \
            &Wh[(size_t)((kk) + row) * NDIM + n0 + c]); }                    \
    CPA_COMMIT();                                                            \
  }

template <int NDIM, int MODE>
__global__ __launch_bounds__(256, 2) void gemm_f16_kernel(
    const float* __restrict__ bias) {
  __shared__ __align__(16) __half sg[18944];

  const __half* __restrict__ Ah = (MODE == 1) ? g_xh : g_ctxh;
  const __half* __restrict__ Wh = (MODE == 1) ? g_wqkvh : g_wouth;

  const int t    = threadIdx.x;
  const int lane = t & 31;
  const int lq   = lane >> 2;
  const int lt   = lane & 3;
  const int warp = t >> 5;
  const int wm   = warp >> 1;   // 0..3 -> 32 rows each
  const int wn   = warp & 1;    // 0..1 -> 64 cols each
  const int n0   = blockIdx.x * 128;
  const int m0   = blockIdx.y * 128;

  const int l8  = lane & 7;
  const int mhi = (lane >> 3) & 1;
  const int mvh = (lane >> 4) & 1;

  float acc[2][8][4];
#pragma unroll
  for (int mt = 0; mt < 2; mt++)
#pragma unroll
    for (int nt = 0; nt < 8; nt++)
#pragma unroll
      for (int j = 0; j < 4; j++) acc[mt][nt][j] = 0.0f;

  GEMM_ISSUE(0, 0)
  CPA_WAIT0();
  __syncthreads();

  for (int it = 0; it < G_NIT; it++) {
    const int s = it & 1;
    if (it + 1 < G_NIT) GEMM_ISSUE(1 - s, (it + 1) * 32)

    const int sA = s * 5120;
    const int sB = 10240 + s * 4352;
#pragma unroll
    for (int ks = 0; ks < 2; ks++) {
      const int kb = ks * 16;
      unsigned a0[4], a1[4];
      {
        const int rowA = wm * 32 + mhi * 8 + l8;
        const int kA   = kb + mvh * 8;
        LDSM4(a0[0], a0[1], a0[2], a0[3], SMEM_U32(&sg[sA + rowA * 40 + kA]));
        LDSM4(a1[0], a1[1], a1[2], a1[3],
              SMEM_U32(&sg[sA + (rowA + 16) * 40 + kA]));
      }
#pragma unroll
      for (int ng = 0; ng < 4; ng++) {
        const int krow = kb + mhi * 8 + l8;
        const int nB   = wn * 64 + ng * 16 + mvh * 8;
        unsigned b0, b1, b2, b3;
        LDSM4T(b0, b1, b2, b3, SMEM_U32(&sg[sB + krow * 136 + nB]));
        const int nt0 = ng * 2, nt1 = ng * 2 + 1;
        MMA_F16(acc[0][nt0][0], acc[0][nt0][1], acc[0][nt0][2], acc[0][nt0][3],
                a0[0], a0[1], a0[2], a0[3], b0, b1);
        MMA_F16(acc[1][nt0][0], acc[1][nt0][1], acc[1][nt0][2], acc[1][nt0][3],
                a1[0], a1[1], a1[2], a1[3], b0, b1);
        MMA_F16(acc[0][nt1][0], acc[0][nt1][1], acc[0][nt1][2], acc[0][nt1][3],
                a0[0], a0[1], a0[2], a0[3], b2, b3);
        MMA_F16(acc[1][nt1][0], acc[1][nt1][1], acc[1][nt1][2], acc[1][nt1][3],
                a1[0], a1[1], a1[2], a1[3], b2, b3);
      }
    }
    if (it + 1 < G_NIT) CPA_WAIT0();
    __syncthreads();
  }

  // Epilogue
#pragma unroll
  for (int mt = 0; mt < 2; mt++) {
    const int r0 = m0 + wm * 32 + mt * 16 + lq;
#pragma unroll
    for (int nt = 0; nt < 8; nt++) {
      const int c0 = n0 + wn * 64 + nt * 8 + lt * 2;
      float v0 = acc[mt][nt][0] + bias[c0];
      float v1 = acc[mt][nt][1] + bias[c0 + 1];
      float v2 = acc[mt][nt][2] + bias[c0];
      float v3 = acc[mt][nt][3] + bias[c0 + 1];
      if (MODE == 0) {
        g_proj[(size_t)r0 * Dn + c0]           = v0;
        g_proj[(size_t)r0 * Dn + c0 + 1]       = v1;
        g_proj[(size_t)(r0 + 8) * Dn + c0]     = v2;
        g_proj[(size_t)(r0 + 8) * Dn + c0 + 1] = v3;
      } else {
        scatter_qkv(r0, c0, v0);
        scatter_qkv(r0, c0 + 1, v1);
        scatter_qkv(r0 + 8, c0, v2);
        scatter_qkv(r0 + 8, c0 + 1, v3);
      }
    }
  }
}

// ---------------------------------------------------------------------------
// Flash attention (FA2, register softmax, Q frags hoisted, ldmatrix,
// cp.async double-buffered K/V).
// Smem halfs: Q [128][88] at 0; stage s: K at 11264+s*11264, V at +5632.
// Total 33792 halfs = 67584 B.
// ---------------------------------------------------------------------------
#define ATTN_SMEM_BYTES 67584
#define A_NIT (Sn / 64)

#define ATT_ISSUE(s, kk)                                                     \
  {                                                                          \
    const int ksb_ = 11264 + (s) * 11264;                                    \
    const int vsb_ = ksb_ + 5632;                                            \
    { int idx = t;       int row = idx >> 3, c = (idx & 7) * 8;              \
      CPA16(SMEM_U32(&smh[ksb_ + row * 88 + c]),                             \
            &g_kh[baseQK + (size_t)((kk) + row) * HDn + c]);                 \
      CPA16(SMEM_U32(&smh[vsb_ + row * 88 + c]),                             \
            &g_vh[baseV + (size_t)row * Sn + (kk) + c]); }                   \
    { int idx = t + 256; int row = idx >> 3, c = (idx & 7) * 8;              \
      CPA16(SMEM_U32(&smh[ksb_ + row * 88 + c]),                             \
            &g_kh[baseQK + (size_t)((kk) + row) * HDn + c]);                 \
      CPA16(SMEM_U32(&smh[vsb_ + row * 88 + c]),                             \
            &g_vh[baseV + (size_t)row * Sn + (kk) + c]); }                   \
    CPA_COMMIT();                                                            \
  }

__global__ __launch_bounds__(256) void attn_f16_kernel() {
  extern __shared__ __align__(16) __half smh[];

  const int t    = threadIdx.x;
  const int lane = t & 31;
  const int warp = t >> 5;
  const int rw   = warp * 16;
  const int b    = blockIdx.z;
  const int h    = blockIdx.y;
  const int sQ   = blockIdx.x * 128;

  const int l8  = lane & 7;
  const int mhi = (lane >> 3) & 1;
  const int mvh = (lane >> 4) & 1;

  const size_t baseQK = (size_t)(b * Hn + h) * Sn * HDn;
  const size_t baseV  = (size_t)(b * Hn + h) * HDn * Sn;

  // Q tile plain copy
#pragma unroll
  for (int i = 0; i < 4; i++) {
    int idx = t + i * 256;
    int row = idx >> 3, c = (idx & 7) * 8;
    *(uint4*)&smh[row * 88 + c] =
        *(const uint4*)&g_qh[baseQK + (size_t)(sQ + row) * HDn + c];
  }

  ATT_ISSUE(0, 0)
  CPA_WAIT0();
  __syncthreads();

  // Hoist Q A-fragments
  unsigned qa[4][4];
#pragma unroll
  for (int ks = 0; ks < 4; ks++) {
    const int rowQ = rw + mhi * 8 + l8;
    const int kQ   = ks * 16 + mvh * 8;
    LDSM4(qa[ks][0], qa[ks][1], qa[ks][2], qa[ks][3],
          SMEM_U32(&smh[rowQ * 88 + kQ]));
  }

  float m0 = -INFINITY, m1 = -INFINITY, l0 = 0.0f, l1 = 0.0f;
  float o[8][4];
#pragma unroll
  for (int nd = 0; nd < 8; nd++)
#pragma unroll
    for (int j = 0; j < 4; j++) o[nd][j] = 0.0f;

  for (int it = 0; it < A_NIT; it++) {
    const int ksb = 11264 + (it & 1) * 11264;
    const int vsb = ksb + 5632;
    if (it + 1 < A_NIT) ATT_ISSUE((it + 1) & 1, (it + 1) * 64)

    // S = Q K^T
    float sa[8][4];
#pragma unroll
    for (int nt = 0; nt < 8; nt++)
#pragma unroll
      for (int j = 0; j < 4; j++) sa[nt][j] = 0.0f;

#pragma unroll
    for (int ks = 0; ks < 4; ks++) {
#pragma unroll
      for (int ng = 0; ng < 4; ng++) {
        const int nrow = ng * 16 + mvh * 8 + l8;
        const int kofs = ks * 16 + mhi * 8;
        unsigned b0, b1, b2, b3;
        LDSM4(b0, b1, b2, b3, SMEM_U32(&smh[ksb + nrow * 88 + kofs]));
        const int nt0 = ng * 2, nt1 = ng * 2 + 1;
        MMA_F16(sa[nt0][0], sa[nt0][1], sa[nt0][2], sa[nt0][3],
                qa[ks][0], qa[ks][1], qa[ks][2], qa[ks][3], b0, b1);
        MMA_F16(sa[nt1][0], sa[nt1][1], sa[nt1][2], sa[nt1][3],
                qa[ks][0], qa[ks][1], qa[ks][2], qa[ks][3], b2, b3);
      }
    }

    // Register softmax
    float mx0 = -INFINITY, mx1 = -INFINITY;
#pragma unroll
    for (int nt = 0; nt < 8; nt++) {
      mx0 = fmaxf(mx0, fmaxf(sa[nt][0], sa[nt][1]));
      mx1 = fmaxf(mx1, fmaxf(sa[nt][2], sa[nt][3]));
    }
    mx0 = fmaxf(mx0, __shfl_xor_sync(0xffffffffu, mx0, 1));
    mx0 = fmaxf(mx0, __shfl_xor_sync(0xffffffffu, mx0, 2));
    mx1 = fmaxf(mx1, __shfl_xor_sync(0xffffffffu, mx1, 1));
    mx1 = fmaxf(mx1, __shfl_xor_sync(0xffffffffu, mx1, 2));
    const float mn0 = fmaxf(m0, mx0);
    const float mn1 = fmaxf(m1, mx1);
    const float cr0 = __expf(m0 - mn0);
    const float cr1 = __expf(m1 - mn1);
    m0 = mn0; m1 = mn1;

    float sum0 = 0.0f, sum1 = 0.0f;
#pragma unroll
    for (int nt = 0; nt < 8; nt++) {
      sa[nt][0] = __expf(sa[nt][0] - mn0);
      sa[nt][1] = __expf(sa[nt][1] - mn0);
      sa[nt][2] = __expf(sa[nt][2] - mn1);
      sa[nt][3] = __expf(sa[nt][3] - mn1);
      sum0 += sa[nt][0] + sa[nt][1];
      sum1 += sa[nt][2] + sa[nt][3];
    }
    sum0 += __shfl_xor_sync(0xffffffffu, sum0, 1);
    sum0 += __shfl_xor_sync(0xffffffffu, sum0, 2);
    sum1 += __shfl_xor_sync(0xffffffffu, sum1, 1);
    sum1 += __shfl_xor_sync(0xffffffffu, sum1, 2);
    l0 = l0 * cr0 + sum0;
    l1 = l1 * cr1 + sum1;

#pragma unroll
    for (int nd = 0; nd < 8; nd++) {
      o[nd][0] *= cr0; o[nd][1] *= cr0;
      o[nd][2] *= cr1; o[nd][3] *= cr1;
    }

    // O += P @ V
#pragma unroll
    for (int kp = 0; kp < 4; kp++) {
      unsigned pa0, pa1, pa2, pa3;
      F22H(pa0, sa[2 * kp][0], sa[2 * kp][1]);
      F22H(pa1, sa[2 * kp][2], sa[2 * kp][3]);
      F22H(pa2, sa[2 * kp + 1][0], sa[2 * kp + 1][1]);
      F22H(pa3, sa[2 * kp + 1][2], sa[2 * kp + 1][3]);
#pragma unroll
      for (int ng = 0; ng < 4; ng++) {
        const int drow = ng * 16 + mvh * 8 + l8;
        const int kofs = kp * 16 + mhi * 8;
        unsigned b0, b1, b2, b3;
        LDSM4(b0, b1, b2, b3, SMEM_U32(&smh[vsb + drow * 88 + kofs]));
        const int nd0 = ng * 2, nd1 = ng * 2 + 1;
        MMA_F16(o[nd0][0], o[nd0][1], o[nd0][2], o[nd0][3],
                pa0, pa1, pa2, pa3, b0, b1);
        MMA_F16(o[nd1][0], o[nd1][1], o[nd1][2], o[nd1][3],
                pa0, pa1, pa2, pa3, b2, b3);
      }
    }

    if (it + 1 < A_NIT) CPA_WAIT0();
    __syncthreads();
  }

  const int lq = lane >> 2;
  const int lt = lane & 3;
  const float i0 = 1.0f / l0;
  const float i1 = 1.0f / l1;
  const size_t row0 = (size_t)(b * Sn + sQ + rw + lq) * Dn + h * HDn;
  const size_t row1 = (size_t)(b * Sn + sQ + rw + lq + 8) * Dn + h * HDn;
#pragma unroll
  for (int nd = 0; nd < 8; nd++) {
    const int c = nd * 8 + lt * 2;
    unsigned u0, u1;
    F22H(u0, o[nd][0] * i0, o[nd][1] * i0);
    F22H(u1, o[nd][2] * i1, o[nd][3] * i1);
    *(unsigned*)&g_ctxh[row0 + c] = u0;
    *(unsigned*)&g_ctxh[row1 + c] = u1;
  }
}

// ---------------------------------------------------------------------------
// Residual + LayerNorm (fp32, unchanged)
// ---------------------------------------------------------------------------
__device__ __forceinline__ float block_sum(float v, float* red) {
#pragma unroll
  for (int o = 16; o; o >>= 1) v += __shfl_xor_sync(0xffffffffu, v, o);
  if ((threadIdx.x & 31) == 0) red[threadIdx.x >> 5] = v;
  __syncthreads();
  float tot = red[0] + red[1] + red[2] + red[3] +
              red[4] + red[5] + red[6] + red[7];
  __syncthreads();
  return tot;
}

__global__ __launch_bounds__(256) void ln_kernel(
    const float* __restrict__ x, const float* __restrict__ gamma,
    const float* __restrict__ beta, float* __restrict__ out) {
  __shared__ float red[8];
  const int row = blockIdx.x;
  const int c   = threadIdx.x * 4;

  float4 y  = *(const float4*)&g_proj[(size_t)row * Dn + c];
  float4 xv = *(const float4*)&x[(size_t)row * Dn + c];
  y.x += xv.x; y.y += xv.y; y.z += xv.z; y.w += xv.w;

  float tot = block_sum(y.x + y.y + y.z + y.w, red);
  const float mu = tot * (1.0f / Dn);

  float dx = y.x - mu, dy = y.y - mu, dz = y.z - mu, dw = y.w - mu;
  float sq = block_sum(dx * dx + dy * dy + dz * dz + dw * dw, red);
  const float var = sq * (1.0f / Dn);
  const float r = rsqrtf(var + 1e-5f);

  float4 g  = *(const float4*)&gamma[c];
  float4 bt = *(const float4*)&beta[c];
  float4 o;
  o.x = dx * r * g.x + bt.x;
  o.y = dy * r * g.y + bt.y;
  o.z = dz * r * g.z + bt.z;
  o.w = dw * r * g.w + bt.w;
  *(float4*)&out[(size_t)row * Dn + c] = o;
}

// ---------------------------------------------------------------------------
// Launch — only harness pointers cross the host/device boundary.
// ---------------------------------------------------------------------------
extern "C" void kernel_launch(void* const* d_in, const int* in_sizes, int n_in,
                              void* d_out, int out_size) {
  (void)in_sizes; (void)n_in; (void)out_size;
  const float* x     = (const float*)d_in[0];
  const float* W_qkv = (const float*)d_in[1];
  const float* b_qkv = (const float*)d_in[2];
  const float* W_out = (const float*)d_in[3];
  const float* b_out = (const float*)d_in[4];
  const float* gamma = (const float*)d_in[5];
  const float* beta  = (const float*)d_in[6];
  float* out = (float*)d_out;

  cudaFuncSetAttribute(attn_f16_kernel,
                       cudaFuncAttributeMaxDynamicSharedMemorySize,
                       ATTN_SMEM_BYTES);

  cvt_x_kernel<<<(Bn * Sn * Dn) / 1024, 256>>>(x);
  cvt_w_kernel<1><<<(Dn * N3) / 1024, 256>>>(W_qkv);
  cvt_w_kernel<0><<<(Dn * Dn) / 1024, 256>>>(W_out);

  gemm_f16_kernel<N3, 1>
      <<<dim3(N3 / 128, (Bn * Sn) / 128), 256>>>(b_qkv);
  attn_f16_kernel<<<dim3(Sn / 128, Hn, Bn), 256, ATTN_SMEM_BYTES>>>();
  gemm_f16_kernel<Dn, 0>
      <<<dim3(Dn / 128, (Bn * Sn) / 128), 256>>>(b_out);
  ln_kernel<<<Bn * Sn, 256>>>(x, gamma, beta, out);
}